// round 3
// baseline (speedup 1.0000x reference)
#include <cuda_runtime.h>
#include <stdint.h>

// Device-global scratch (no allocations allowed).
// g_tab[mp] = lut[q(mp)] * s_x for mp = round(log2(x_int + bias)) in [0, 31].
__device__ float g_tab[32];
__device__ float g_params[2];   // [0] = 1/s_x, [1] = bias

// ---------------------------------------------------------------------------
// Setup: build the 32-entry remap table with IEEE-exact fp32 arithmetic,
// faithfully replicating the reference fp32 op order:
//   y      = (-mp) * c            (c = round(2^(16-0.7)) = 40342)
//   scale  = (maxv - minv) / 15
//   zp     = round(-minv / scale)
//   q      = clip(round(y/scale) + zp, 0, 15)
//   out    = lut[q] * s_x
// __fdiv_rn / rintf give IEEE div + round-half-even independent of
// --use_fast_math, matching XLA's fp32 semantics (the odd-mp quotients land
// exactly on .5 ties and resolve half-even; verified against measured error).
// ---------------------------------------------------------------------------
__global__ void lsq_setup_kernel(const float* __restrict__ s_x,
                                 const float* __restrict__ bias,
                                 const float* __restrict__ minv,
                                 const float* __restrict__ maxv,
                                 const float* __restrict__ lut) {
    if (threadIdx.x == 0 && blockIdx.x == 0) {
        const float sx = *s_x;
        const float mn = *minv;
        const float mx = *maxv;
        const float c  = 40342.0f;                       // rint(2^15.3)
        const float scale = __fdiv_rn(mx - mn, 15.0f);
        const float zp    = rintf(__fdiv_rn(-mn, scale));
        #pragma unroll
        for (int mp = 0; mp < 32; ++mp) {
            float y  = (float)(-mp) * c;
            float qf = rintf(__fdiv_rn(y, scale)) + zp;
            qf = fminf(fmaxf(qf, 0.0f), 15.0f);
            g_tab[mp] = lut[(int)qf] * sx;
        }
        g_params[0] = __fdiv_rn(1.0f, sx);   // exact: s_x is a power of two
        g_params[1] = *bias;
    }
}

// ---------------------------------------------------------------------------
// mp = round(log2(v)) computed EXACTLY over the integer v:
//   n = floor(log2 v);  mp = n + (v*v >= 2^(2n+1))
// (ties impossible: 2^(n+0.5) is irrational). v|1 is used ONLY inside clz as
// a v==0 guard — the squared value uses the true v. (Round-1 bug: squaring
// v|1 corrupted every even v adjacent to a decade boundary.)
// The v=46341 case (log2 = 15.5000016) belongs to mp=16, which this exact
// threshold gives natively — no exception.
// ---------------------------------------------------------------------------
__device__ __forceinline__ int lsq_mp(float x, float inv_sx, float bias) {
    float vf = rintf(x * inv_sx) + bias;       // x_int + bias (exact integers)
    unsigned v = (unsigned)vf;
    int n = 31 - __clz(v | 1u);                // guard clz(0) only
    unsigned long long vv = (unsigned long long)v * (unsigned long long)v;
    return n + (int)(vv >> (2 * n + 1));       // shifted value is 0 or 1
}

__global__ void __launch_bounds__(256)
lsq_main_kernel(const float4* __restrict__ in, float4* __restrict__ out, int n4) {
    __shared__ float s_tab[32];
    if (threadIdx.x < 32) s_tab[threadIdx.x] = g_tab[threadIdx.x];
    __syncthreads();

    int i = blockIdx.x * blockDim.x + threadIdx.x;
    if (i >= n4) return;
    const float inv_sx = g_params[0];
    const float bias   = g_params[1];
    float4 x = __ldg(&in[i]);
    float4 r;
    r.x = s_tab[lsq_mp(x.x, inv_sx, bias)];
    r.y = s_tab[lsq_mp(x.y, inv_sx, bias)];
    r.z = s_tab[lsq_mp(x.z, inv_sx, bias)];
    r.w = s_tab[lsq_mp(x.w, inv_sx, bias)];
    out[i] = r;
}

// Fill any trailing output elements (tuple second element: s_x scalar).
__global__ void lsq_tail_kernel(float* __restrict__ out,
                                const float* __restrict__ s_x,
                                int start, int total) {
    int i = start + blockIdx.x * blockDim.x + threadIdx.x;
    if (i < total) out[i] = *s_x;
}

extern "C" void kernel_launch(void* const* d_in, const int* in_sizes, int n_in,
                              void* d_out, int out_size) {
    const float* x_hat = (const float*)d_in[0];
    const float* s_x   = (const float*)d_in[1];
    const float* bias  = (const float*)d_in[2];
    const float* minv  = (const float*)d_in[3];
    const float* maxv  = (const float*)d_in[4];
    const float* lut   = (const float*)d_in[5];
    float* out = (float*)d_out;

    const int n = in_sizes[0];

    lsq_setup_kernel<<<1, 32>>>(s_x, bias, minv, maxv, lut);

    const int n4 = n >> 2;                       // N divisible by 4
    const int threads = 256;
    const int blocks = (n4 + threads - 1) / threads;
    lsq_main_kernel<<<blocks, threads>>>((const float4*)x_hat, (float4*)out, n4);

    if (out_size > n) {
        int tail = out_size - n;
        int tthreads = 128;
        int tblocks = (tail + tthreads - 1) / tthreads;
        lsq_tail_kernel<<<tblocks, tthreads>>>(out, s_x, n, out_size);
    }
}